// round 8
// baseline (speedup 1.0000x reference)
#include <cuda_runtime.h>

#define HH 256
#define WW 256
#define BB 2
#define CC 4
#define NROWS (BB*HH)        // 512 blocks, one per (b,h) row
#define NWARPS (NROWS*8)     // 4096 warps total
#define NTOT (BB*CC*HH*WW)   // 524288
#define FPS 4096.0f
#define INV_FPS (1.0f/4096.0f)

// Padded accumulators: one 128B line each -> independent L2 atomic ALUs.
struct __align__(128) PadInt { int v; int pad[31]; };
__device__ PadInt gA;                 // zero-initialized
__device__ PadInt gS[2*CC];
__device__ PadInt gM[2*CC];
__device__ unsigned int g_cnt;        // self-resetting

__device__ __forceinline__ int labAt(const int* __restrict__ y, int shift,
                                     int idx) {
    return __ldg(&y[idx << shift]);
}

__global__ void __launch_bounds__(256) rw_fused(const int* __restrict__ y,
                                                const float* __restrict__ x,
                                                float* __restrict__ out) {
    const int r    = blockIdx.x;      // b*256 + h
    const int b    = r >> 8;
    const int h    = r & 255;
    const int w    = threadIdx.x;     // column
    const int lane = w & 31;
    const int hw   = (h << 8) + w;
    const int base = b << 16;

    // ---- round 1: x loads + dtype sniff word (all independent) ----
    float xv[CC];
    #pragma unroll
    for (int c = 0; c < CC; c++)
        xv[c] = __ldg(&x[((b * CC + c) << 16) + hw]);

    // words 1,3,..,63 in-bounds under either dtype; int64 LE => all zero
    int odd = __ldg(&y[2 * lane + 1]);
    const int shift = __all_sync(0xffffffffu, odd == 0) ? 1 : 0;

    // ---- 3x3 label window, per-thread, clamped (no smem, no barrier) ----
    const int hm = h > 0 ? h - 1 : 0,  hp = h < HH-1 ? h + 1 : HH-1;
    const int wm = w > 0 ? w - 1 : 0,  wp = w < WW-1 ? w + 1 : WW-1;
    const int rowm = base + (hm << 8), row0 = base + (h << 8), rowp = base + (hp << 8);
    int l00 = labAt(y, shift, rowm + wm);
    int l01 = labAt(y, shift, rowm + w );
    int l02 = labAt(y, shift, rowm + wp);
    int l10 = labAt(y, shift, row0 + wm);
    int L   = labAt(y, shift, row0 + w );
    int l12 = labAt(y, shift, row0 + wp);
    int l20 = labAt(y, shift, rowp + wm);
    int l21 = labAt(y, shift, rowp + w );
    int l22 = labAt(y, shift, rowp + wp);

    // ---- softmax (x-only) overlaps the label-window latency ----
    float e1 = __expf(xv[1] - xv[0]);
    float e2 = __expf(xv[2] - xv[0]);
    float e3 = __expf(xv[3] - xv[0]);
    float inv = __frcp_rn(1.0f + e1 + e2 + e3);
    float p0 = inv, p1 = e1 * inv, p2 = e2 * inv, p3 = e3 * inv;

    // ---- d^2 to nearest differing label (integer-exact) ----
    bool ax = (w > 0     && l10 != L) || (w < WW-1 && l12 != L) ||
              (h > 0     && l01 != L) || (h < HH-1 && l21 != L);
    int best;
    if (ax) {
        best = 1;
    } else {
        bool dg = false;
        if (h > 0) {
            if (w > 0    && l00 != L) dg = true;
            if (w < WW-1 && l02 != L) dg = true;
        }
        if (h < HH-1) {
            if (w > 0    && l20 != L) dg = true;
            if (w < WW-1 && l22 != L) dg = true;
        }
        best = dg ? 2 : 0x7fffffff;
        // Rare general rings (needs 3x3 uniform patch: p ~ 4^-8)
        for (int R = 2; R < 512 && R * R < best; R++) {
            int hmr = h - R, hpr = h + R, wmr = w - R, wpr = w + R;
            int wlo = wmr < 0 ? 0 : wmr, whi = wpr > WW-1 ? WW-1 : wpr;
            if (hmr >= 0)
                for (int ww = wlo; ww <= whi; ww++)
                    if (labAt(y, shift, base + hmr * WW + ww) != L) {
                        int dw = ww - w, d2 = R*R + dw*dw;
                        if (d2 < best) best = d2;
                    }
            if (hpr <= HH-1)
                for (int ww = wlo; ww <= whi; ww++)
                    if (labAt(y, shift, base + hpr * WW + ww) != L) {
                        int dw = ww - w, d2 = R*R + dw*dw;
                        if (d2 < best) best = d2;
                    }
            int hlo = hmr + 1 < 0 ? 0 : hmr + 1;
            int hhi = hpr - 1 > HH-1 ? HH-1 : hpr - 1;
            if (wmr >= 0)
                for (int hh = hlo; hh <= hhi; hh++)
                    if (labAt(y, shift, base + hh * WW + wmr) != L) {
                        int dh = hh - h, d2 = R*R + dh*dh;
                        if (d2 < best) best = d2;
                    }
            if (wpr <= WW-1)
                for (int hh = hlo; hh <= hhi; hh++)
                    if (labAt(y, shift, base + hh * WW + wpr) != L) {
                        int dh = hh - h, d2 = R*R + dh*dh;
                        if (d2 < best) best = d2;
                    }
        }
    }

    float pL = (L == 0) ? p0 : (L == 1) ? p1 : (L == 2) ? p2 : p3;
    float sd = (best == 1) ? 1.0f
             : (best == 2) ? 1.41421356237f
             : sqrtf((float)best);

    // ---- fixed-point warp reduction (REDUX; result in all lanes) ----
    int ai = __reduce_add_sync(0xffffffffu, __float2int_rn((1.0f - pL) * FPS));
    int si = __float2int_rn(pL * sd * FPS);
    int wS[CC], wM[CC];
    #pragma unroll
    for (int c = 0; c < CC; c++) {
        wS[c] = __reduce_add_sync(0xffffffffu, (L == c) ? si : 0);
        wM[c] = __reduce_max_sync(0xffffffffu, (L == c) ? best : 0);
    }

    // ---- direct global commit: 9 lanes, 9 distinct padded addresses ----
    if (lane == 0)            atomicAdd(&gA.v, ai);
    else if (lane <= CC)      atomicAdd(&gS[b * CC + lane - 1].v, wS[lane - 1]);
    else if (lane <= 2*CC)    atomicMax(&gM[b * CC + lane - 1 - CC].v, wM[lane - 1 - CC]);

    // Warp-uniform fence: orders the warp's commits before lane 0's bump.
    __threadfence();

    if (lane == 0) {
        unsigned int old = atomicAdd(&g_cnt, 1u);
        if (old == NWARPS - 1) {
            __threadfence();   // acquire side
            float res = (float)__ldcg(&gA.v) * INV_FPS;
            #pragma unroll
            for (int k = 0; k < 2*CC; k++) {
                float Sk = (float)__ldcg(&gS[k].v) * INV_FPS;
                float Mk = (float)__ldcg(&gM[k].v);
                res -= Sk / (sqrtf(Mk) + 1e-15f);
            }
            out[0] = res * (1.0f / (float)NTOT);
            // reset for next graph replay
            gA.v = 0;
            #pragma unroll
            for (int k = 0; k < 2*CC; k++) { gS[k].v = 0; gM[k].v = 0; }
            __threadfence();
            g_cnt = 0;
        }
    }
}

// ---------------------------------------------------------------------------
extern "C" void kernel_launch(void* const* d_in, const int* in_sizes, int n_in,
                              void* d_out, int out_size) {
    const float* x;
    const void*  y;
    if (in_sizes[0] == NTOT) { x = (const float*)d_in[0]; y = d_in[1]; }
    else                     { x = (const float*)d_in[1]; y = d_in[0]; }

    rw_fused<<<NROWS, 256>>>((const int*)y, x, (float*)d_out);
}

// round 9
// speedup vs baseline: 1.5394x; 1.5394x over previous
#include <cuda_runtime.h>

#define HH 256
#define WW 256
#define BB 2
#define CC 4
#define NROWS (BB*HH)        // 512 blocks, one per (b,h) row
#define NTOT (BB*CC*HH*WW)   // 524288
#define FPS 4096.0f
#define INV_FPS (1.0f/4096.0f)

// Global integer accumulators (zero-init; last block resets after each run)
__device__ int gA = 0;
__device__ int gS[2*CC] = {0,0,0,0,0,0,0,0};
__device__ int gM[2*CC] = {0,0,0,0,0,0,0,0};
__device__ unsigned int g_cnt = 0;

__device__ __forceinline__ int labAt(const int* __restrict__ y, int shift,
                                     int b, int idx) {
    return y[((b << 16) + idx) << shift];
}

// exp(dx) via 2^(dx*log2e), FFMA/ALU only (no MUFU). |dx| <~ 30 safe.
// rel err < 1e-5 (deg-6 Taylor on f in [0,1)).
__device__ __forceinline__ float fexp(float dx) {
    float t  = dx * 1.4426950408889634f;
    int   ni = __float2int_rd(t);
    float f  = t - (float)ni;
    float p  = 1.5403530393e-4f;
    p = fmaf(p, f, 1.3333558146e-3f);
    p = fmaf(p, f, 9.6181291076e-3f);
    p = fmaf(p, f, 5.5504108664e-2f);
    p = fmaf(p, f, 2.4022650696e-1f);
    p = fmaf(p, f, 6.9314718056e-1f);
    p = fmaf(p, f, 1.0f);
    return __int_as_float((ni + 127) << 23) * p;
}

__global__ void __launch_bounds__(256) rw_fused(const int* __restrict__ y,
                                                const float* __restrict__ x,
                                                float* __restrict__ out) {
    __shared__ int sl[3][WW];            // label rows h-1, h, h+1
    __shared__ int sA, sS[CC], sM[CC];
    __shared__ int s_last;

    const int r    = blockIdx.x;         // b*256 + h
    const int b    = r >> 8;
    const int h    = r & 255;
    const int w    = threadIdx.x;
    const int lane = w & 31;
    const int hw   = (h << 8) + w;

    // ---- round 1: x loads + per-warp dtype sniff (one memory round) ----
    float xv[CC];
    #pragma unroll
    for (int c = 0; c < CC; c++)
        xv[c] = __ldg(&x[((b * CC + c) << 16) + hw]);

    // words 1,3,..,63 in-bounds under either dtype; int64 LE => all zero
    int odd   = __ldg(&y[2 * lane + 1]);
    int is64  = __all_sync(0xffffffffu, odd == 0);
    const int shift = is64 ? 1 : 0;

    if (w < CC)   { sS[w] = 0; sM[w] = 0; }
    if (w == 32)  sA = 0;

    // ---- round 2: stage 3 label rows ----
    #pragma unroll
    for (int k = 0; k < 3; k++) {
        int hh = h - 1 + k;
        if (hh >= 0 && hh < HH)
            sl[k][w] = labAt(y, shift, b, (hh << 8) + w);
    }
    __syncthreads();

    const int L = sl[1][w];

    // ---- d^2 to nearest differing label (integer-exact ring search) ----
    int best;
    bool ax = (w > 0      && sl[1][w-1] != L) ||
              (w < WW-1   && sl[1][w+1] != L) ||
              (h > 0      && sl[0][w]   != L) ||
              (h < HH-1   && sl[2][w]   != L);
    if (ax) {
        best = 1;
    } else {
        bool dg = false;
        if (h > 0) {
            if (w > 0    && sl[0][w-1] != L) dg = true;
            if (w < WW-1 && sl[0][w+1] != L) dg = true;
        }
        if (h < HH-1) {
            if (w > 0    && sl[2][w-1] != L) dg = true;
            if (w < WW-1 && sl[2][w+1] != L) dg = true;
        }
        best = dg ? 2 : 0x7fffffff;
        // Rare general rings (needs a 3x3 uniform patch: p ~ 4^-8)
        for (int R = 2; R < 512 && R * R < best; R++) {
            int hm = h - R, hp = h + R, wm = w - R, wp = w + R;
            int wlo = wm < 0 ? 0 : wm, whi = wp > WW-1 ? WW-1 : wp;
            if (hm >= 0)
                for (int ww = wlo; ww <= whi; ww++)
                    if (labAt(y, shift, b, hm * WW + ww) != L) {
                        int dw = ww - w, d2 = R*R + dw*dw;
                        if (d2 < best) best = d2;
                    }
            if (hp <= HH-1)
                for (int ww = wlo; ww <= whi; ww++)
                    if (labAt(y, shift, b, hp * WW + ww) != L) {
                        int dw = ww - w, d2 = R*R + dw*dw;
                        if (d2 < best) best = d2;
                    }
            int hlo = hm + 1 < 0 ? 0 : hm + 1;
            int hhi = hp - 1 > HH-1 ? HH-1 : hp - 1;
            if (wm >= 0)
                for (int hh = hlo; hh <= hhi; hh++)
                    if (labAt(y, shift, b, hh * WW + wm) != L) {
                        int dh = hh - h, d2 = R*R + dh*dh;
                        if (d2 < best) best = d2;
                    }
            if (wp <= WW-1)
                for (int hh = hlo; hh <= hhi; hh++)
                    if (labAt(y, shift, b, hh * WW + wp) != L) {
                        int dh = hh - h, d2 = R*R + dh*dh;
                        if (d2 < best) best = d2;
                    }
        }
    }

    // ---- softmax p_L: FFMA-only exps relative to class 0, 1 MUFU rcp ----
    float e1 = fexp(xv[1] - xv[0]);
    float e2 = fexp(xv[2] - xv[0]);
    float e3 = fexp(xv[3] - xv[0]);
    float eL = (L == 0) ? 1.0f : (L == 1) ? e1 : (L == 2) ? e2 : e3;
    float pL = eL * __frcp_rn(1.0f + e1 + e2 + e3);

    float sd = (best == 1) ? 1.0f
             : (best == 2) ? 1.41421356237f
             : sqrtf((float)best);

    // ---- fixed-point warp reduction (REDUX) ----
    int ai = __reduce_add_sync(0xffffffffu, __float2int_rn((1.0f - pL) * FPS));
    int si = __float2int_rn(pL * sd * FPS);
    int wS[CC], wM[CC];
    #pragma unroll
    for (int c = 0; c < CC; c++) {
        wS[c] = __reduce_add_sync(0xffffffffu, (L == c) ? si : 0);
        wM[c] = __reduce_max_sync(0xffffffffu, (L == c) ? best : 0);
    }
    if (lane == 0) {
        atomicAdd(&sA, ai);
        #pragma unroll
        for (int c = 0; c < CC; c++) {
            atomicAdd(&sS[c], wS[c]);
            atomicMax(&sM[c], wM[c]);
        }
    }
    __syncthreads();

    // ---- commit block partials straight to global accumulators ----
    if (w == 0)            atomicAdd(&gA, sA);
    else if (w < 1 + CC)   atomicAdd(&gS[b * CC + (w - 1)], sS[w - 1]);
    else if (w < 1 + 2*CC) atomicMax(&gM[b * CC + (w - 1 - CC)], sM[w - 1 - CC]);

    __threadfence();
    if (w == 0) {
        unsigned int old = atomicAdd(&g_cnt, 1u);
        s_last = (old == NROWS - 1);
    }
    __syncthreads();
    if (!s_last) return;

    // ---- last block: 17-value finalize + reset for graph replay ----
    if (w == 0) {
        float res = (float)__ldcg(&gA) * INV_FPS;
        #pragma unroll
        for (int k = 0; k < 2*CC; k++) {
            float Sk = (float)__ldcg(&gS[k]) * INV_FPS;
            float Mk = (float)__ldcg(&gM[k]);
            res -= Sk / (sqrtf(Mk) + 1e-15f);
        }
        out[0] = res * (1.0f / (float)NTOT);
        gA = 0;
        #pragma unroll
        for (int k = 0; k < 2*CC; k++) { gS[k] = 0; gM[k] = 0; }
        __threadfence();
        g_cnt = 0;
    }
}

// ---------------------------------------------------------------------------
extern "C" void kernel_launch(void* const* d_in, const int* in_sizes, int n_in,
                              void* d_out, int out_size) {
    const float* x;
    const void*  y;
    if (in_sizes[0] == NTOT) { x = (const float*)d_in[0]; y = d_in[1]; }
    else                     { x = (const float*)d_in[1]; y = d_in[0]; }

    rw_fused<<<NROWS, 256>>>((const int*)y, x, (float*)d_out);
}

// round 11
// speedup vs baseline: 1.5761x; 1.0239x over previous
#include <cuda_runtime.h>

#define HH 256
#define WW 256
#define BB 2
#define CC 4
#define NROWS (BB*HH)        // 512 blocks, one per (b,h) row
#define NTOT (BB*CC*HH*WW)   // 524288
#define FPS 4096.0f
#define INV_FPS (1.0f/4096.0f)

// Global integer accumulators (zero-init; last block resets after each run)
__device__ int gA = 0;
__device__ int gS[2*CC] = {0,0,0,0,0,0,0,0};
__device__ int gM[2*CC] = {0,0,0,0,0,0,0,0};
__device__ unsigned int g_cnt = 0;

__device__ __forceinline__ int labAt(const int* __restrict__ y, int shift,
                                     int b, int idx) {
    return y[((b << 16) + idx) << shift];
}

__global__ void __launch_bounds__(256) rw_fused(const int* __restrict__ y,
                                                const float* __restrict__ x,
                                                float* __restrict__ out) {
    __shared__ int sl[3][WW];            // label rows h-1, h, h+1
    __shared__ int sA, sS[CC], sM[CC];
    __shared__ int s_last;

    const int r    = blockIdx.x;         // b*256 + h
    const int b    = r >> 8;
    const int h    = r & 255;
    const int w    = threadIdx.x;
    const int lane = w & 31;
    const int hw   = (h << 8) + w;

    // ---- ONE memory round: x + sniff + BOTH label layouts (11 LDGs) ----
    float xv[CC];
    #pragma unroll
    for (int c = 0; c < CC; c++)
        xv[c] = __ldg(&x[((b * CC + c) << 16) + hw]);

    // sniff word (odd words in-bounds under either dtype; int64 LE => 0)
    int odd = __ldg(&y[2 * lane + 1]);

    // speculative label loads: clamped rows h-1,h,h+1; both layouts
    int lab64[3], lab32[3];
    #pragma unroll
    for (int k = 0; k < 3; k++) {
        int hh = h - 1 + k;
        hh = hh < 0 ? 0 : (hh > HH-1 ? HH-1 : hh);
        int idx = (b << 16) + (hh << 8) + w;
        lab64[k] = __ldg(&y[idx << 1]);  // int64 layout (low word)
        lab32[k] = __ldg(&y[idx]);       // int32 layout
    }

    const int is64  = __all_sync(0xffffffffu, odd == 0);
    const int shift = is64 ? 1 : 0;

    if (w < CC)   { sS[w] = 0; sM[w] = 0; }
    if (w == 32)  sA = 0;

    // ---- select + stage rows in smem ----
    #pragma unroll
    for (int k = 0; k < 3; k++)
        sl[k][w] = is64 ? lab64[k] : lab32[k];
    __syncthreads();

    const int L = sl[1][w];

    // ---- d^2 to nearest differing label (integer-exact ring search) ----
    int best;
    bool ax = (w > 0      && sl[1][w-1] != L) ||
              (w < WW-1   && sl[1][w+1] != L) ||
              (h > 0      && sl[0][w]   != L) ||
              (h < HH-1   && sl[2][w]   != L);
    if (ax) {
        best = 1;
    } else {
        bool dg = false;
        if (h > 0) {
            if (w > 0    && sl[0][w-1] != L) dg = true;
            if (w < WW-1 && sl[0][w+1] != L) dg = true;
        }
        if (h < HH-1) {
            if (w > 0    && sl[2][w-1] != L) dg = true;
            if (w < WW-1 && sl[2][w+1] != L) dg = true;
        }
        best = dg ? 2 : 0x7fffffff;
        // Rare general rings (needs a 3x3 uniform patch: p ~ 4^-8)
        for (int R = 2; R < 512 && R * R < best; R++) {
            int hm = h - R, hp = h + R, wm = w - R, wp = w + R;
            int wlo = wm < 0 ? 0 : wm, whi = wp > WW-1 ? WW-1 : wp;
            if (hm >= 0)
                for (int ww = wlo; ww <= whi; ww++)
                    if (labAt(y, shift, b, hm * WW + ww) != L) {
                        int dw = ww - w, d2 = R*R + dw*dw;
                        if (d2 < best) best = d2;
                    }
            if (hp <= HH-1)
                for (int ww = wlo; ww <= whi; ww++)
                    if (labAt(y, shift, b, hp * WW + ww) != L) {
                        int dw = ww - w, d2 = R*R + dw*dw;
                        if (d2 < best) best = d2;
                    }
            int hlo = hm + 1 < 0 ? 0 : hm + 1;
            int hhi = hp - 1 > HH-1 ? HH-1 : hp - 1;
            if (wm >= 0)
                for (int hh = hlo; hh <= hhi; hh++)
                    if (labAt(y, shift, b, hh * WW + wm) != L) {
                        int dh = hh - h, d2 = R*R + dh*dh;
                        if (d2 < best) best = d2;
                    }
            if (wp <= WW-1)
                for (int hh = hlo; hh <= hhi; hh++)
                    if (labAt(y, shift, b, hh * WW + wp) != L) {
                        int dh = hh - h, d2 = R*R + dh*dh;
                        if (d2 < best) best = d2;
                    }
        }
    }

    // ---- softmax p_L: exps relative to class 0 ----
    float e1 = __expf(xv[1] - xv[0]);
    float e2 = __expf(xv[2] - xv[0]);
    float e3 = __expf(xv[3] - xv[0]);
    float eL = (L == 0) ? 1.0f : (L == 1) ? e1 : (L == 2) ? e2 : e3;
    float pL = eL * __frcp_rn(1.0f + e1 + e2 + e3);

    float sd = (best == 1) ? 1.0f
             : (best == 2) ? 1.41421356237f
             : sqrtf((float)best);

    // ---- fixed-point warp reduction (REDUX) ----
    int ai = __reduce_add_sync(0xffffffffu, __float2int_rn((1.0f - pL) * FPS));
    int si = __float2int_rn(pL * sd * FPS);
    int wS[CC], wM[CC];
    #pragma unroll
    for (int c = 0; c < CC; c++) {
        wS[c] = __reduce_add_sync(0xffffffffu, (L == c) ? si : 0);
        wM[c] = __reduce_max_sync(0xffffffffu, (L == c) ? best : 0);
    }
    if (lane == 0) {
        atomicAdd(&sA, ai);
        #pragma unroll
        for (int c = 0; c < CC; c++) {
            atomicAdd(&sS[c], wS[c]);
            atomicMax(&sM[c], wM[c]);
        }
    }
    __syncthreads();

    // ---- commit block partials straight to global accumulators ----
    if (w == 0)            atomicAdd(&gA, sA);
    else if (w < 1 + CC)   atomicAdd(&gS[b * CC + (w - 1)], sS[w - 1]);
    else if (w < 1 + 2*CC) atomicMax(&gM[b * CC + (w - 1 - CC)], sM[w - 1 - CC]);

    __threadfence();
    if (w == 0) {
        unsigned int old = atomicAdd(&g_cnt, 1u);
        s_last = (old == NROWS - 1);
    }
    __syncthreads();
    if (!s_last) return;

    // ---- last block: serial 17-value finalize + reset (proven in R6) ----
    if (w == 0) {
        float res = (float)__ldcg(&gA) * INV_FPS;
        #pragma unroll
        for (int k = 0; k < 2*CC; k++) {
            float Sk = (float)__ldcg(&gS[k]) * INV_FPS;
            float Mk = (float)__ldcg(&gM[k]);
            res -= Sk / (sqrtf(Mk) + 1e-15f);
        }
        out[0] = res * (1.0f / (float)NTOT);
        gA = 0;
        #pragma unroll
        for (int k = 0; k < 2*CC; k++) { gS[k] = 0; gM[k] = 0; }
        __threadfence();
        g_cnt = 0;
    }
}

// ---------------------------------------------------------------------------
extern "C" void kernel_launch(void* const* d_in, const int* in_sizes, int n_in,
                              void* d_out, int out_size) {
    const float* x;
    const void*  y;
    if (in_sizes[0] == NTOT) { x = (const float*)d_in[0]; y = d_in[1]; }
    else                     { x = (const float*)d_in[1]; y = d_in[0]; }

    rw_fused<<<NROWS, 256>>>((const int*)y, x, (float*)d_out);
}